// round 17
// baseline (speedup 1.0000x reference)
#include <cuda_runtime.h>

// Problem constants (fixed by the reference: B=8, S=2048, D=1024)
#define BB 8
#define SS 2048
#define DD 1024
#define CHUNKS 64
#define ROWS_PER_CHUNK (SS / CHUNKS)   // 32
#define GEMV_CTAS 128                   // <= #SMs -> all co-resident

#define FIXED_SCALE 4294967296.0        // 2^32 fixed-point scale
#define INV_FIXED_SCALE (1.0 / 4294967296.0)

// Fixed-point accumulators: zero at module load; re-zeroed by kernel B's
// last CTA each call (replay-safe). Integer adds are order-independent ->
// bitwise-deterministic output regardless of atomic arrival order.
__device__ unsigned long long g_acc[BB * DD];   // 64 KB
__device__ int g_cnt;                           // staging-complete counter

// ---------------------------------------------------------------------------
// Kernel A: per-(batch, chunk) column sum of x over S. [measured-good body]
// grid = (64, 8) = 512 CTAs, block = 256; thread t owns float4 column t.
// Tail: each thread converts its 4 chunk-partials to int64 fixed-point and
// atomicAdds into the global accumulators (order-independent -> deterministic,
// replaces the 2 MB partial round-trip + kernel B's reduce phase + spin).
// ---------------------------------------------------------------------------
__global__ __launch_bounds__(256) void colsum_kernel(const float* __restrict__ x) {
    const int c = blockIdx.x;
    const int b = blockIdx.y;
    const int t = threadIdx.x;

    const float4* __restrict__ xp =
        reinterpret_cast<const float4*>(x + ((size_t)b * SS + (size_t)c * ROWS_PER_CHUNK) * DD) + t;

    float4 a0 = make_float4(0.f, 0.f, 0.f, 0.f);
    float4 a1 = make_float4(0.f, 0.f, 0.f, 0.f);
    float4 a2 = make_float4(0.f, 0.f, 0.f, 0.f);
    float4 a3 = make_float4(0.f, 0.f, 0.f, 0.f);

    #pragma unroll
    for (int s = 0; s < ROWS_PER_CHUNK; s += 8) {
        float4 v0 = xp[(size_t)(s + 0) * (DD / 4)];
        float4 v1 = xp[(size_t)(s + 1) * (DD / 4)];
        float4 v2 = xp[(size_t)(s + 2) * (DD / 4)];
        float4 v3 = xp[(size_t)(s + 3) * (DD / 4)];
        float4 v4 = xp[(size_t)(s + 4) * (DD / 4)];
        float4 v5 = xp[(size_t)(s + 5) * (DD / 4)];
        float4 v6 = xp[(size_t)(s + 6) * (DD / 4)];
        float4 v7 = xp[(size_t)(s + 7) * (DD / 4)];
        a0.x += v0.x; a0.y += v0.y; a0.z += v0.z; a0.w += v0.w;
        a1.x += v1.x; a1.y += v1.y; a1.z += v1.z; a1.w += v1.w;
        a2.x += v2.x; a2.y += v2.y; a2.z += v2.z; a2.w += v2.w;
        a3.x += v3.x; a3.y += v3.y; a3.z += v3.z; a3.w += v3.w;
        a0.x += v4.x; a0.y += v4.y; a0.z += v4.z; a0.w += v4.w;
        a1.x += v5.x; a1.y += v5.y; a1.z += v5.z; a1.w += v5.w;
        a2.x += v6.x; a2.y += v6.y; a2.z += v6.z; a2.w += v6.w;
        a3.x += v7.x; a3.y += v7.y; a3.z += v7.z; a3.w += v7.w;
    }

    float4 acc;
    acc.x = (a0.x + a1.x) + (a2.x + a3.x);
    acc.y = (a0.y + a1.y) + (a2.y + a3.y);
    acc.z = (a0.z + a1.z) + (a2.z + a3.z);
    acc.w = (a0.w + a1.w) + (a2.w + a3.w);

    // Fixed-point accumulate (int64 adds commute -> deterministic).
    unsigned long long* __restrict__ dst = g_acc + (size_t)b * DD + t * 4;
    atomicAdd(dst + 0, (unsigned long long)(long long)__double2ll_rn((double)acc.x * FIXED_SCALE));
    atomicAdd(dst + 1, (unsigned long long)(long long)__double2ll_rn((double)acc.y * FIXED_SCALE));
    atomicAdd(dst + 2, (unsigned long long)(long long)__double2ll_rn((double)acc.z * FIXED_SCALE));
    atomicAdd(dst + 3, (unsigned long long)(long long)__double2ll_rn((double)acc.w * FIXED_SCALE));
}

// Accumulate one float4 column across all 8 batches (fixed order).
__device__ __forceinline__ void acc_col(const float* __restrict__ xs, int c4,
                                        const float4& w,
                                        float& s0, float& s1, float& s2, float& s3,
                                        float& s4, float& s5, float& s6, float& s7) {
    const float4* __restrict__ xsv = reinterpret_cast<const float4*>(xs);
    float4 x0 = xsv[0 * (DD / 4) + c4];
    float4 x1 = xsv[1 * (DD / 4) + c4];
    float4 x2 = xsv[2 * (DD / 4) + c4];
    float4 x3 = xsv[3 * (DD / 4) + c4];
    float4 x4 = xsv[4 * (DD / 4) + c4];
    float4 x5 = xsv[5 * (DD / 4) + c4];
    float4 x6 = xsv[6 * (DD / 4) + c4];
    float4 x7 = xsv[7 * (DD / 4) + c4];
    s0 += w.x * x0.x + w.y * x0.y + w.z * x0.z + w.w * x0.w;
    s1 += w.x * x1.x + w.y * x1.y + w.z * x1.z + w.w * x1.w;
    s2 += w.x * x2.x + w.y * x2.y + w.z * x2.z + w.w * x2.w;
    s3 += w.x * x3.x + w.y * x3.y + w.z * x3.z + w.w * x3.w;
    s4 += w.x * x4.x + w.y * x4.y + w.z * x4.z + w.w * x4.w;
    s5 += w.x * x5.x + w.y * x5.y + w.z * x5.z + w.w * x5.w;
    s6 += w.x * x6.x + w.y * x6.y + w.z * x6.z + w.w * x6.w;
    s7 += w.x * x7.x + w.y * x7.y + w.z * x7.z + w.w * x7.w;
}

// ---------------------------------------------------------------------------
// Kernel B: gemv straight from the finished fixed-point accumulators.
// grid = 128 CTAs, block = 256. NO cross-CTA dependency before output:
//   prefetch Wv row + bv (registers)
//   stage: load g_acc (64 KB), convert fixed->float into smem xs
//   arrival count (g_cnt) -- the LAST CTA to stage re-zeroes g_acc for the
//     next replay and resets the counter (overlapped with others' gemv,
//     off the output critical path)
//   gemv: warp owns Wv row e, dots against all 8 batches (preloaded Wv)
// ---------------------------------------------------------------------------
__global__ __launch_bounds__(256) void gemv_kernel(const float* __restrict__ Wv,
                                                   const float* __restrict__ bv,
                                                   float* __restrict__ out) {
    __shared__ float xs[BB * DD];   // 32 KB
    __shared__ int s_last;

    const int t    = threadIdx.x;
    const int cta  = blockIdx.x;    // 0..127
    const int warp = t >> 5;
    const int lane = t & 31;
    const int e = cta * 8 + warp;   // output feature owned by this warp

    // ---- Prefetch: Wv row + bias (overlaps the staging loads) ----------
    const float4* __restrict__ wrow = reinterpret_cast<const float4*>(Wv + (size_t)e * DD);
    float4 w0 = wrow[lane +   0];
    float4 w1 = wrow[lane +  32];
    float4 w2 = wrow[lane +  64];
    float4 w3 = wrow[lane +  96];
    float4 w4 = wrow[lane + 128];
    float4 w5 = wrow[lane + 160];
    float4 w6 = wrow[lane + 192];
    float4 w7 = wrow[lane + 224];
    const float bias = (float)SS * bv[e];

    // ---- Stage: fixed-point -> float into smem (8192 values, 32/thread) -
    #pragma unroll
    for (int i = 0; i < (BB * DD) / 256; ++i) {     // 32 iterations
        const int idx = t + 256 * i;
        long long q = (long long)g_acc[idx];
        xs[idx] = (float)((double)q * INV_FIXED_SCALE);
    }
    __syncthreads();

    // ---- Arrival count; last CTA zeroes accumulators for next replay ----
    if (t == 0) {
        int o = atomicAdd(&g_cnt, 1);
        s_last = (o == GEMV_CTAS - 1) ? 1 : 0;
    }
    __syncthreads();
    if (s_last) {
        // All 128 CTAs have finished reading g_acc -> safe to zero.
        #pragma unroll
        for (int i = 0; i < (BB * DD) / 256; ++i)
            g_acc[t + 256 * i] = 0ull;
        __syncthreads();
        if (t == 0) {
            __threadfence();
            atomicExch(&g_cnt, 0);
        }
    }

    // ---- gemv using preloaded Wv registers ------------------------------
    float s0 = 0.f, s1 = 0.f, s2 = 0.f, s3 = 0.f;
    float s4 = 0.f, s5 = 0.f, s6 = 0.f, s7 = 0.f;

    acc_col(xs, lane +   0, w0, s0, s1, s2, s3, s4, s5, s6, s7);
    acc_col(xs, lane +  32, w1, s0, s1, s2, s3, s4, s5, s6, s7);
    acc_col(xs, lane +  64, w2, s0, s1, s2, s3, s4, s5, s6, s7);
    acc_col(xs, lane +  96, w3, s0, s1, s2, s3, s4, s5, s6, s7);
    acc_col(xs, lane + 128, w4, s0, s1, s2, s3, s4, s5, s6, s7);
    acc_col(xs, lane + 160, w5, s0, s1, s2, s3, s4, s5, s6, s7);
    acc_col(xs, lane + 192, w6, s0, s1, s2, s3, s4, s5, s6, s7);
    acc_col(xs, lane + 224, w7, s0, s1, s2, s3, s4, s5, s6, s7);

    #pragma unroll
    for (int off = 16; off; off >>= 1) {
        s0 += __shfl_xor_sync(0xffffffffu, s0, off);
        s1 += __shfl_xor_sync(0xffffffffu, s1, off);
        s2 += __shfl_xor_sync(0xffffffffu, s2, off);
        s3 += __shfl_xor_sync(0xffffffffu, s3, off);
        s4 += __shfl_xor_sync(0xffffffffu, s4, off);
        s5 += __shfl_xor_sync(0xffffffffu, s5, off);
        s6 += __shfl_xor_sync(0xffffffffu, s6, off);
        s7 += __shfl_xor_sync(0xffffffffu, s7, off);
    }

    if (lane == 0) {
        out[0 * DD + e] = s0 + bias;
        out[1 * DD + e] = s1 + bias;
        out[2 * DD + e] = s2 + bias;
        out[3 * DD + e] = s3 + bias;
        out[4 * DD + e] = s4 + bias;
        out[5 * DD + e] = s5 + bias;
        out[6 * DD + e] = s6 + bias;
        out[7 * DD + e] = s7 + bias;
    }
}

// ---------------------------------------------------------------------------
// kernel_launch — graph-capturable, allocation-free, deterministic.
// Input order (metadata): 0=x, 1=Wq, 2=bq, 3=Wk, 4=bk, 5=Wv, 6=bv
// ---------------------------------------------------------------------------
extern "C" void kernel_launch(void* const* d_in, const int* in_sizes, int n_in,
                              void* d_out, int out_size) {
    (void)in_sizes; (void)n_in; (void)out_size;
    const float* x  = (const float*)d_in[0];
    const float* Wv = (const float*)d_in[5];
    const float* bv = (const float*)d_in[6];
    float* out = (float*)d_out;

    colsum_kernel<<<dim3(CHUNKS, BB), 256>>>(x);
    gemv_kernel<<<GEMV_CTAS, 256>>>(Wv, bv, out);
}